// round 2
// baseline (speedup 1.0000x reference)
#include <cuda_runtime.h>
#include <math.h>

#define BSZ 8
#define SEQ 1024
#define DIM 1024
#define NH 16
#define DH 64
#define MTOK (BSZ*SEQ)        // 8192
#define FFD  (2*DIM)          // 2048

typedef unsigned long long ull;

// ---------------- scratch (device globals; no runtime allocation) ----------
__device__ float g_q[MTOK*DIM];
__device__ float g_k[MTOK*DIM];
__device__ float g_v[MTOK*DIM];
__device__ float g_attn[MTOK*DIM];
__device__ float g_h1[MTOK*DIM];
__device__ float g_ffn[MTOK*FFD];

__device__ __forceinline__ void ffma2(ull& c, ull a, ull b) {
    asm("fma.rn.f32x2 %0, %1, %2, %0;" : "+l"(c) : "l"(a), "l"(b));
}
__device__ __forceinline__ float2 unpack2(ull u) {
    float2 f;
    asm("mov.b64 {%0, %1}, %2;" : "=f"(f.x), "=f"(f.y) : "l"(u));
    return f;
}

// ---------------- NT GEMM with packed f32x2 FMA --------------------------
// C[M,N] = (A[M,K] * B[N,K]^T + bias) * scale (+res) (+relu)
// hmode=1: per-head batched scores gemm: A=q, B=k (lda=ldb=DIM, slice h*64),
//          C = score + z*SEQ*SEQ, K=64, N=SEQ.
__global__ __launch_bounds__(256) void gemm_nt_x2(
    const float* __restrict__ A, const float* __restrict__ Bw,
    const float* __restrict__ bias, const float* __restrict__ res,
    float* __restrict__ C, int M, int N, int K, float scale, int relu, int hmode)
{
    __shared__ float AsD[16][256];   // A values duplicated along M
    __shared__ float Bs[16][128];

    if (hmode) {
        const int b = blockIdx.z >> 4, h = blockIdx.z & 15;
        A  += (size_t)b * SEQ * DIM + h * DH;
        Bw += (size_t)b * SEQ * DIM + h * DH;
        C  += (size_t)blockIdx.z * SEQ * SEQ;
    }
    const int lda = hmode ? DIM : K;
    const int ldb = hmode ? DIM : K;

    const int n0 = blockIdx.x * 128;
    const int m0 = blockIdx.y * 128;
    const int tid = threadIdx.x;
    const int tx = tid & 15, ty = tid >> 4;

    ull acc2[8][4];
#pragma unroll
    for (int i = 0; i < 8; i++)
#pragma unroll
        for (int j = 0; j < 4; j++) acc2[i][j] = 0ull;

    const int lrow = tid >> 1;        // 0..127
    const int lc   = (tid & 1) * 4;   // 0 or 4
    const float* Aptr = A  + (size_t)(m0 + lrow) * lda + lc;
    const float* Bptr = Bw + (size_t)(n0 + lrow) * ldb + lc;

    for (int kt = 0; kt < K; kt += 16) {
#pragma unroll
        for (int h2 = 0; h2 < 2; h2++) {
            float4 av = *(const float4*)(Aptr + kt + h2 * 8);
            float4 bv = *(const float4*)(Bptr + kt + h2 * 8);
            const int kk = h2 * 8 + lc;
            *(float2*)&AsD[kk+0][2*lrow] = make_float2(av.x, av.x);
            *(float2*)&AsD[kk+1][2*lrow] = make_float2(av.y, av.y);
            *(float2*)&AsD[kk+2][2*lrow] = make_float2(av.z, av.z);
            *(float2*)&AsD[kk+3][2*lrow] = make_float2(av.w, av.w);
            Bs[kk+0][lrow] = bv.x; Bs[kk+1][lrow] = bv.y;
            Bs[kk+2][lrow] = bv.z; Bs[kk+3][lrow] = bv.w;
        }
        __syncthreads();
#pragma unroll
        for (int k = 0; k < 16; k++) {
            ulonglong2 a0 = *(const ulonglong2*)&AsD[k][ty*16];
            ulonglong2 a1 = *(const ulonglong2*)&AsD[k][ty*16 + 4];
            ulonglong2 a2 = *(const ulonglong2*)&AsD[k][ty*16 + 8];
            ulonglong2 a3 = *(const ulonglong2*)&AsD[k][ty*16 + 12];
            ulonglong2 b0 = *(const ulonglong2*)&Bs[k][tx*8];
            ulonglong2 b1 = *(const ulonglong2*)&Bs[k][tx*8 + 4];
            ull ap[8] = {a0.x, a0.y, a1.x, a1.y, a2.x, a2.y, a3.x, a3.y};
            ull bp[4] = {b0.x, b0.y, b1.x, b1.y};
#pragma unroll
            for (int i = 0; i < 8; i++)
#pragma unroll
                for (int j = 0; j < 4; j++)
                    ffma2(acc2[i][j], ap[i], bp[j]);
        }
        __syncthreads();
    }

    // epilogue
#pragma unroll
    for (int i = 0; i < 8; i++) {
        const int m = m0 + ty*8 + i;
        const int nb = n0 + tx*8;
        float o[8];
#pragma unroll
        for (int j = 0; j < 4; j++) {
            float2 f = unpack2(acc2[i][j]);
            o[2*j] = f.x; o[2*j+1] = f.y;
        }
        if (bias) {
            float4 b0 = *(const float4*)&bias[nb];
            float4 b1 = *(const float4*)&bias[nb + 4];
            o[0]+=b0.x; o[1]+=b0.y; o[2]+=b0.z; o[3]+=b0.w;
            o[4]+=b1.x; o[5]+=b1.y; o[6]+=b1.z; o[7]+=b1.w;
        }
        if (scale != 1.f) {
#pragma unroll
            for (int j = 0; j < 8; j++) o[j] *= scale;
        }
        if (res) {
            float4 r0 = *(const float4*)&res[(size_t)m*N + nb];
            float4 r1 = *(const float4*)&res[(size_t)m*N + nb + 4];
            o[0]+=r0.x; o[1]+=r0.y; o[2]+=r0.z; o[3]+=r0.w;
            o[4]+=r1.x; o[5]+=r1.y; o[6]+=r1.z; o[7]+=r1.w;
        }
        if (relu) {
#pragma unroll
            for (int j = 0; j < 8; j++) o[j] = fmaxf(o[j], 0.f);
        }
        *(float4*)&C[(size_t)m*N + nb]     = make_float4(o[0],o[1],o[2],o[3]);
        *(float4*)&C[(size_t)m*N + nb + 4] = make_float4(o[4],o[5],o[6],o[7]);
    }
}

// ---------------- softmax over rows of s, last column masked (-inf -> 0) ---
__global__ __launch_bounds__(256) void softmax_mask_last(float* __restrict__ s)
{
    __shared__ float sm[8];
    const size_t base = (size_t)blockIdx.x * SEQ;
    const int tid = threadIdx.x;
    const int lane = tid & 31, wid = tid >> 5;

    float4 v = *(const float4*)&s[base + tid*4];
    const bool haslast = (tid == 255);
    if (haslast) v.w = -INFINITY;

    float m = fmaxf(fmaxf(v.x, v.y), fmaxf(v.z, v.w));
#pragma unroll
    for (int o = 16; o; o >>= 1) m = fmaxf(m, __shfl_xor_sync(0xffffffffu, m, o));
    if (lane == 0) sm[wid] = m;
    __syncthreads();
    if (tid == 0) {
        float t = sm[0];
#pragma unroll
        for (int i = 1; i < 8; i++) t = fmaxf(t, sm[i]);
        sm[0] = t;
    }
    __syncthreads();
    const float mall = sm[0];
    __syncthreads();

    float e0 = __expf(v.x - mall);
    float e1 = __expf(v.y - mall);
    float e2 = __expf(v.z - mall);
    float e3 = haslast ? 0.f : __expf(v.w - mall);
    float ssum = e0 + e1 + e2 + e3;
#pragma unroll
    for (int o = 16; o; o >>= 1) ssum += __shfl_xor_sync(0xffffffffu, ssum, o);
    if (lane == 0) sm[wid] = ssum;
    __syncthreads();
    if (tid == 0) {
        float t = 0.f;
#pragma unroll
        for (int i = 0; i < 8; i++) t += sm[i];
        sm[0] = t;
    }
    __syncthreads();
    const float inv = 1.f / sm[0];

    *(float4*)&s[base + tid*4] = make_float4(e0*inv, e1*inv, e2*inv, e3*inv);
}

// ---------------- PV with packed f32x2: o = P[bh] @ V[b,:,h*64:...] --------
__global__ __launch_bounds__(256) void attn_pv_x2(
    const float* __restrict__ p, const float* __restrict__ v, float* __restrict__ o)
{
    __shared__ float PsD[16][256];   // P duplicated along M
    __shared__ float Vs[16][64];
    const int bh = blockIdx.y;
    const int b = bh >> 4, h = bh & 15;
    const int m0 = blockIdx.x * 128;
    const int tid = threadIdx.x;
    const int tx = tid & 15, ty = tid >> 4;

    ull acc2[8][2];
#pragma unroll
    for (int i = 0; i < 8; i++) { acc2[i][0] = 0ull; acc2[i][1] = 0ull; }

    for (int kt = 0; kt < SEQ; kt += 16) {
#pragma unroll
        for (int it = 0; it < 2; it++) {
            int lin = it * 256 + tid;
            int arow = lin >> 2;           // 0..127
            int c4 = (lin & 3) * 4;        // 0,4,8,12
            float4 av = *(const float4*)&p[((size_t)bh*SEQ + m0 + arow)*SEQ + kt + c4];
            *(float2*)&PsD[c4+0][2*arow] = make_float2(av.x, av.x);
            *(float2*)&PsD[c4+1][2*arow] = make_float2(av.y, av.y);
            *(float2*)&PsD[c4+2][2*arow] = make_float2(av.z, av.z);
            *(float2*)&PsD[c4+3][2*arow] = make_float2(av.w, av.w);
        }
        {
            int krow = tid >> 4;           // 0..15
            int c4 = (tid & 15) * 4;
            float4 bv = *(const float4*)&v[((size_t)(b*SEQ + kt + krow))*DIM + h*DH + c4];
            *(float4*)&Vs[krow][c4] = bv;
        }
        __syncthreads();
#pragma unroll
        for (int k = 0; k < 16; k++) {
            ulonglong2 a0 = *(const ulonglong2*)&PsD[k][ty*16];
            ulonglong2 a1 = *(const ulonglong2*)&PsD[k][ty*16 + 4];
            ulonglong2 a2 = *(const ulonglong2*)&PsD[k][ty*16 + 8];
            ulonglong2 a3 = *(const ulonglong2*)&PsD[k][ty*16 + 12];
            ulonglong2 bq = *(const ulonglong2*)&Vs[k][tx*4];
            ull ap[8] = {a0.x, a0.y, a1.x, a1.y, a2.x, a2.y, a3.x, a3.y};
#pragma unroll
            for (int i = 0; i < 8; i++) {
                ffma2(acc2[i][0], ap[i], bq.x);
                ffma2(acc2[i][1], ap[i], bq.y);
            }
        }
        __syncthreads();
    }

#pragma unroll
    for (int i = 0; i < 8; i++) {
        float2 f0 = unpack2(acc2[i][0]);
        float2 f1 = unpack2(acc2[i][1]);
        size_t idx = ((size_t)(b*SEQ + m0 + ty*8 + i))*DIM + h*DH + tx*4;
        *(float4*)&o[idx] = make_float4(f0.x, f0.y, f1.x, f1.y);
    }
}

// ---------------- row layernorm --------------------------------------------
__global__ __launch_bounds__(256) void layernorm_row(
    const float* __restrict__ in, float* __restrict__ out,
    const float* __restrict__ g, const float* __restrict__ be)
{
    __shared__ float sm[8], sq[8];
    const size_t base = (size_t)blockIdx.x * DIM;
    const int tid = threadIdx.x;
    const int lane = tid & 31, wid = tid >> 5;

    float4 v = *(const float4*)&in[base + tid*4];
    float s  = v.x + v.y + v.z + v.w;
    float s2 = v.x*v.x + v.y*v.y + v.z*v.z + v.w*v.w;
#pragma unroll
    for (int o = 16; o; o >>= 1) {
        s  += __shfl_xor_sync(0xffffffffu, s,  o);
        s2 += __shfl_xor_sync(0xffffffffu, s2, o);
    }
    if (lane == 0) { sm[wid] = s; sq[wid] = s2; }
    __syncthreads();
    if (tid == 0) {
        float t = 0.f, t2 = 0.f;
#pragma unroll
        for (int i = 0; i < 8; i++) { t += sm[i]; t2 += sq[i]; }
        sm[0] = t; sq[0] = t2;
    }
    __syncthreads();
    const float mean = sm[0] * (1.f / DIM);
    const float var  = sq[0] * (1.f / DIM) - mean * mean;
    const float r = rsqrtf(var + 1e-5f);

    float4 gg = *(const float4*)&g[tid*4];
    float4 bb = *(const float4*)&be[tid*4];
    float4 o4;
    o4.x = (v.x - mean) * r * gg.x + bb.x;
    o4.y = (v.y - mean) * r * gg.y + bb.y;
    o4.z = (v.z - mean) * r * gg.z + bb.z;
    o4.w = (v.w - mean) * r * gg.w + bb.w;
    *(float4*)&out[base + tid*4] = o4;
}

// ---------------- launcher -------------------------------------------------
extern "C" void kernel_launch(void* const* d_in, const int* in_sizes, int n_in,
                              void* d_out, int out_size)
{
    const float* x  = (const float*)d_in[0];
    const float* Wq = (const float*)d_in[1];
    const float* bq = (const float*)d_in[2];
    const float* Wk = (const float*)d_in[3];
    const float* bk = (const float*)d_in[4];
    const float* Wv = (const float*)d_in[5];
    const float* bv = (const float*)d_in[6];
    const float* Wf = (const float*)d_in[7];
    const float* bf = (const float*)d_in[8];
    const float* W1 = (const float*)d_in[9];
    const float* b1 = (const float*)d_in[10];
    const float* W2 = (const float*)d_in[11];
    const float* b2 = (const float*)d_in[12];
    const float* g1 = (const float*)d_in[13];
    const float* be1= (const float*)d_in[14];
    const float* g2 = (const float*)d_in[15];
    const float* be2= (const float*)d_in[16];

    float* out   = (float*)d_out;                      // [8,1024,1024]
    float* score = out + (size_t)MTOK * DIM;           // [8,16,1024,1024]

    float *pq, *pk, *pv, *pattn, *ph1, *pffn;
    cudaGetSymbolAddress((void**)&pq,    g_q);
    cudaGetSymbolAddress((void**)&pk,    g_k);
    cudaGetSymbolAddress((void**)&pv,    g_v);
    cudaGetSymbolAddress((void**)&pattn, g_attn);
    cudaGetSymbolAddress((void**)&ph1,   g_h1);
    cudaGetSymbolAddress((void**)&pffn,  g_ffn);

    const float inv_sqrt_dh = 0.125f; // 1/sqrt(64)

    // QKV projections (q pre-scaled by 1/sqrt(dh), applied after bias like ref)
    gemm_nt_x2<<<dim3(DIM/128, MTOK/128), 256>>>(x, Wq, bq, nullptr, pq, MTOK, DIM, DIM, inv_sqrt_dh, 0, 0);
    gemm_nt_x2<<<dim3(DIM/128, MTOK/128), 256>>>(x, Wk, bk, nullptr, pk, MTOK, DIM, DIM, 1.f, 0, 0);
    gemm_nt_x2<<<dim3(DIM/128, MTOK/128), 256>>>(x, Wv, bv, nullptr, pv, MTOK, DIM, DIM, 1.f, 0, 0);

    // raw scores -> score region of d_out (batched per-head NT gemm)
    gemm_nt_x2<<<dim3(SEQ/128, SEQ/128, BSZ*NH), 256>>>(pq, pk, nullptr, nullptr, score, SEQ, SEQ, DH, 1.f, 0, 1);
    softmax_mask_last<<<BSZ*NH*SEQ, 256>>>(score);
    attn_pv_x2<<<dim3(SEQ/128, BSZ*NH), 256>>>(score, pv, pattn);

    // output projection + residual, then LN1
    gemm_nt_x2<<<dim3(DIM/128, MTOK/128), 256>>>(pattn, Wf, bf, x, ph1, MTOK, DIM, DIM, 1.f, 0, 0);
    layernorm_row<<<MTOK, 256>>>(ph1, ph1, g1, be1);

    // FFN
    gemm_nt_x2<<<dim3(FFD/128, MTOK/128), 256>>>(ph1, W1, b1, nullptr, pffn, MTOK, FFD, DIM, 1.f, 1, 0);
    gemm_nt_x2<<<dim3(DIM/128, MTOK/128), 256>>>(pffn, W2, b2, ph1, pq, MTOK, DIM, FFD, 1.f, 0, 0);
    layernorm_row<<<MTOK, 256>>>(pq, out, g2, be2);
}

// round 4
// speedup vs baseline: 6.2339x; 6.2339x over previous
#include <cuda_runtime.h>
#include <cstdint>
#include <math.h>

#define BSZ 8
#define SEQ 1024
#define DIM 1024
#define NH 16
#define DH 64
#define MTOK (BSZ*SEQ)        // 8192
#define FFD  (2*DIM)          // 2048

// ---------------- scratch (device globals; no runtime allocation) ----------
__device__ float g_q[MTOK*DIM];
__device__ float g_k[MTOK*DIM];
__device__ float g_v[MTOK*DIM];
__device__ float g_attn[MTOK*DIM];
__device__ float g_h1[MTOK*DIM];
__device__ float g_ffn[MTOK*FFD];

// ================= helpers =================================================
__device__ __forceinline__ uint32_t smem_u32(const void* p) {
    uint32_t a;
    asm("{ .reg .u64 t; cvta.to.shared.u64 t, %1; cvt.u32.u64 %0, t; }"
        : "=r"(a) : "l"(p));
    return a;
}
__device__ __forceinline__ uint32_t cvtf(float x) {
    uint32_t u; asm("cvt.rna.tf32.f32 %0, %1;" : "=r"(u) : "f"(x)); return u;
}
#define CP_ASYNC16(s, g) \
    asm volatile("cp.async.cg.shared.global [%0], [%1], 16;" :: "r"(s), "l"(g))
#define CP_COMMIT() asm volatile("cp.async.commit_group;")
#define CP_WAIT1()  asm volatile("cp.async.wait_group 1;")

__device__ __forceinline__ void mma_tf32(float* d, const uint32_t* a, const uint32_t* b) {
    asm volatile(
        "mma.sync.aligned.m16n8k8.row.col.f32.tf32.tf32.f32 "
        "{%0,%1,%2,%3}, {%4,%5,%6,%7}, {%8,%9}, {%0,%1,%2,%3};"
        : "+f"(d[0]), "+f"(d[1]), "+f"(d[2]), "+f"(d[3])
        : "r"(a[0]), "r"(a[1]), "r"(a[2]), "r"(a[3]), "r"(b[0]), "r"(b[1]));
}

// ================= mma.sync tf32 GEMM ======================================
// C[M,N] = (A[M,K] * B^T + bias) * scale (+res) (+relu)
// MODE 0: plain NT gemm (B is [N,K] row-major).
// MODE 1: per-head scores: A=q,B=k slices (lda=ldb=DIM), C=score+z*SEQ*SEQ.
// MODE 2: PV: A=P [M,K] (lda=SEQ), B=V [K,N] row-major (NN gemm), NT=64.
// CTA tile 128 x NT, K-slab 32, cp.async double buffer.
template <int NT, int MODE>
__global__ __launch_bounds__(256, 2) void gemm_mma(
    const float* __restrict__ A, const float* __restrict__ B,
    const float* __restrict__ bias, const float* __restrict__ res,
    float* __restrict__ C, int K, int lda, int ldb, int ldc,
    float scale, int relu)
{
    constexpr int ASTR = 36;                    // floats, pad: conflict-free frags
    constexpr int BSTR = (MODE == 2) ? 72 : 36;
    constexpr int AFL  = 128 * ASTR;            // 4608 floats per buffer
    constexpr int BFL  = (MODE == 2) ? 32 * BSTR : NT * BSTR;

    constexpr int WROWS = (NT == 128) ? 2 : 4;  // warps along M
    constexpr int WCOLS = 8 / WROWS;            // warps along N
    constexpr int WM = 128 / WROWS;             // 64 / 32
    constexpr int WN = NT / WCOLS;              // 32
    constexpr int MT  = WM / 16;                // m16 tiles per warp
    constexpr int NTg = WN / 8;                 // n8 tiles per warp

    extern __shared__ char dynsmem[];
    float* const AsB = (float*)dynsmem;
    float* const BsB = AsB + 2 * AFL;

    const int tid = threadIdx.x;
    const int wid = tid >> 5, lane = tid & 31;
    const int g = lane >> 2, t = lane & 3;
    const int wm = (wid % WROWS) * WM;
    const int wn = (wid / WROWS) * WN;

    const int n0 = blockIdx.x * NT;
    const int m0 = blockIdx.y * 128;
    const float* Ap; const float* Bp; float* Cp;
    if (MODE == 0) { Ap = A; Bp = B; Cp = C; }
    else if (MODE == 1) {
        const int z = blockIdx.z, b = z >> 4, h = z & 15;
        Ap = A + (size_t)b * SEQ * DIM + h * DH;
        Bp = B + (size_t)b * SEQ * DIM + h * DH;
        Cp = C + (size_t)z * SEQ * SEQ;
    } else {
        const int z = blockIdx.z, b = z >> 4, h = z & 15;
        Ap = A + (size_t)z * SEQ * SEQ;
        Bp = B + (size_t)b * SEQ * DIM + h * DH;
        Cp = C + (size_t)b * SEQ * DIM + h * DH;
    }

    float acc[MT][NTg][4];
#pragma unroll
    for (int i = 0; i < MT; i++)
#pragma unroll
        for (int j = 0; j < NTg; j++)
#pragma unroll
            for (int q = 0; q < 4; q++) acc[i][j][q] = 0.f;

    const int Kc = K >> 5;

    // ---- async load of one K-slab into buffer `buf` ----
    auto load_slab = [&](int c, int buf) {
        const int kt = c << 5;
        float* As = AsB + buf * AFL;
        float* Bs = BsB + buf * BFL;
        // A: 128 rows x 8 16B-chunks = 1024 chunks, 4/thread
#pragma unroll
        for (int i = 0; i < 4; i++) {
            const int lin = i * 256 + tid;
            const int row = lin >> 3, c16 = lin & 7;
            const float* gp = Ap + (size_t)(m0 + row) * lda + kt + c16 * 4;
            CP_ASYNC16(smem_u32(As + row * ASTR + c16 * 4), gp);
        }
        if (MODE != 2) {
            // B: NT rows x 8 chunks
#pragma unroll
            for (int i = 0; i < NT / 32; i++) {
                const int lin = i * 256 + tid;
                const int row = lin >> 3, c16 = lin & 7;
                const float* gp = Bp + (size_t)(n0 + row) * ldb + kt + c16 * 4;
                CP_ASYNC16(smem_u32(Bs + row * BSTR + c16 * 4), gp);
            }
        } else {
            // V: 32 k-rows x 16 chunks (64 floats), natural layout
#pragma unroll
            for (int i = 0; i < 2; i++) {
                const int lin = i * 256 + tid;
                const int krow = lin >> 4, c16 = lin & 15;
                const float* gp = Bp + (size_t)(kt + krow) * ldb + c16 * 4;
                CP_ASYNC16(smem_u32(Bs + krow * BSTR + c16 * 4), gp);
            }
        }
    };

    load_slab(0, 0);
    CP_COMMIT();

    for (int c = 0; c < Kc; c++) {
        if (c + 1 < Kc) load_slab(c + 1, (c + 1) & 1);
        CP_COMMIT();
        CP_WAIT1();
        __syncthreads();

        const float* As = AsB + (c & 1) * AFL;
        const float* Bs = BsB + (c & 1) * BFL;
#pragma unroll
        for (int ks = 0; ks < 4; ks++) {
            const int kk = ks * 8;
            uint32_t af[MT][4];
#pragma unroll
            for (int mt = 0; mt < MT; mt++) {
                const float* ar = As + (wm + mt * 16 + g) * ASTR + kk + t;
                af[mt][0] = cvtf(ar[0]);
                af[mt][1] = cvtf(ar[8 * ASTR]);
                af[mt][2] = cvtf(ar[4]);
                af[mt][3] = cvtf(ar[8 * ASTR + 4]);
            }
            uint32_t bf[NTg][2];
#pragma unroll
            for (int nt = 0; nt < NTg; nt++) {
                if (MODE != 2) {
                    const float* br = Bs + (wn + nt * 8 + g) * BSTR + kk + t;
                    bf[nt][0] = cvtf(br[0]);
                    bf[nt][1] = cvtf(br[4]);
                } else {
                    const float* br = Bs + (kk + t) * BSTR + wn + nt * 8 + g;
                    bf[nt][0] = cvtf(br[0]);
                    bf[nt][1] = cvtf(br[4 * BSTR]);
                }
            }
#pragma unroll
            for (int mt = 0; mt < MT; mt++)
#pragma unroll
                for (int nt = 0; nt < NTg; nt++)
                    mma_tf32(acc[mt][nt], af[mt], bf[nt]);
        }
        __syncthreads();
    }

    // ---- epilogue: fused bias/scale/res/relu, float2 stores ----
#pragma unroll
    for (int mt = 0; mt < MT; mt++) {
        const int row = m0 + wm + mt * 16 + g;
#pragma unroll
        for (int nt = 0; nt < NTg; nt++) {
            const int col = n0 + wn + nt * 8 + 2 * t;
            float o0 = acc[mt][nt][0], o1 = acc[mt][nt][1];
            float o2 = acc[mt][nt][2], o3 = acc[mt][nt][3];
            if (bias) {
                const float b0 = bias[col], b1 = bias[col + 1];
                o0 += b0; o1 += b1; o2 += b0; o3 += b1;
            }
            if (scale != 1.f) { o0 *= scale; o1 *= scale; o2 *= scale; o3 *= scale; }
            if (res) {
                float2 r0 = *(const float2*)&res[(size_t)row * ldc + col];
                float2 r1 = *(const float2*)&res[(size_t)(row + 8) * ldc + col];
                o0 += r0.x; o1 += r0.y; o2 += r1.x; o3 += r1.y;
            }
            if (relu) {
                o0 = fmaxf(o0, 0.f); o1 = fmaxf(o1, 0.f);
                o2 = fmaxf(o2, 0.f); o3 = fmaxf(o3, 0.f);
            }
            *(float2*)&Cp[(size_t)row * ldc + col]       = make_float2(o0, o1);
            *(float2*)&Cp[(size_t)(row + 8) * ldc + col] = make_float2(o2, o3);
        }
    }
}

// ================= softmax (row, last col masked) ==========================
__global__ __launch_bounds__(256) void softmax_mask_last(float* __restrict__ s)
{
    __shared__ float sm[8];
    const size_t base = (size_t)blockIdx.x * SEQ;
    const int tid = threadIdx.x;
    const int lane = tid & 31, wid = tid >> 5;

    float4 v = *(const float4*)&s[base + tid*4];
    const bool haslast = (tid == 255);
    if (haslast) v.w = -INFINITY;

    float m = fmaxf(fmaxf(v.x, v.y), fmaxf(v.z, v.w));
#pragma unroll
    for (int o = 16; o; o >>= 1) m = fmaxf(m, __shfl_xor_sync(0xffffffffu, m, o));
    if (lane == 0) sm[wid] = m;
    __syncthreads();
    if (tid == 0) {
        float tt = sm[0];
#pragma unroll
        for (int i = 1; i < 8; i++) tt = fmaxf(tt, sm[i]);
        sm[0] = tt;
    }
    __syncthreads();
    const float mall = sm[0];
    __syncthreads();

    float e0 = __expf(v.x - mall);
    float e1 = __expf(v.y - mall);
    float e2 = __expf(v.z - mall);
    float e3 = haslast ? 0.f : __expf(v.w - mall);
    float ssum = e0 + e1 + e2 + e3;
#pragma unroll
    for (int o = 16; o; o >>= 1) ssum += __shfl_xor_sync(0xffffffffu, ssum, o);
    if (lane == 0) sm[wid] = ssum;
    __syncthreads();
    if (tid == 0) {
        float tt = 0.f;
#pragma unroll
        for (int i = 0; i < 8; i++) tt += sm[i];
        sm[0] = tt;
    }
    __syncthreads();
    const float inv = 1.f / sm[0];
    *(float4*)&s[base + tid*4] = make_float4(e0*inv, e1*inv, e2*inv, e3*inv);
}

// ================= layernorm ==============================================
__global__ __launch_bounds__(256) void layernorm_row(
    const float* __restrict__ in, float* __restrict__ out,
    const float* __restrict__ g, const float* __restrict__ be)
{
    __shared__ float sm[8], sq[8];
    const size_t base = (size_t)blockIdx.x * DIM;
    const int tid = threadIdx.x;
    const int lane = tid & 31, wid = tid >> 5;

    float4 v = *(const float4*)&in[base + tid*4];
    float s  = v.x + v.y + v.z + v.w;
    float s2 = v.x*v.x + v.y*v.y + v.z*v.z + v.w*v.w;
#pragma unroll
    for (int o = 16; o; o >>= 1) {
        s  += __shfl_xor_sync(0xffffffffu, s,  o);
        s2 += __shfl_xor_sync(0xffffffffu, s2, o);
    }
    if (lane == 0) { sm[wid] = s; sq[wid] = s2; }
    __syncthreads();
    if (tid == 0) {
        float tt = 0.f, t2 = 0.f;
#pragma unroll
        for (int i = 0; i < 8; i++) { tt += sm[i]; t2 += sq[i]; }
        sm[0] = tt; sq[0] = t2;
    }
    __syncthreads();
    const float mean = sm[0] * (1.f / DIM);
    const float var  = sq[0] * (1.f / DIM) - mean * mean;
    const float r = rsqrtf(var + 1e-5f);

    float4 gg = *(const float4*)&g[tid*4];
    float4 bb = *(const float4*)&be[tid*4];
    float4 o4;
    o4.x = (v.x - mean) * r * gg.x + bb.x;
    o4.y = (v.y - mean) * r * gg.y + bb.y;
    o4.z = (v.z - mean) * r * gg.z + bb.z;
    o4.w = (v.w - mean) * r * gg.w + bb.w;
    *(float4*)&out[base + tid*4] = o4;
}

// ================= launcher ================================================
static const int SMEM_NT128 = 2 * (128*36 + 128*36) * 4;  // 73728
static const int SMEM_PV    = (2 * 128*36 + 2 * 32*72) * 4;  // 55296

extern "C" void kernel_launch(void* const* d_in, const int* in_sizes, int n_in,
                              void* d_out, int out_size)
{
    const float* x  = (const float*)d_in[0];
    const float* Wq = (const float*)d_in[1];
    const float* bq = (const float*)d_in[2];
    const float* Wk = (const float*)d_in[3];
    const float* bk = (const float*)d_in[4];
    const float* Wv = (const float*)d_in[5];
    const float* bv = (const float*)d_in[6];
    const float* Wf = (const float*)d_in[7];
    const float* bf = (const float*)d_in[8];
    const float* W1 = (const float*)d_in[9];
    const float* b1 = (const float*)d_in[10];
    const float* W2 = (const float*)d_in[11];
    const float* b2 = (const float*)d_in[12];
    const float* g1 = (const float*)d_in[13];
    const float* be1= (const float*)d_in[14];
    const float* g2 = (const float*)d_in[15];
    const float* be2= (const float*)d_in[16];

    float* out   = (float*)d_out;
    float* score = out + (size_t)MTOK * DIM;

    float *pq, *pk, *pv, *pattn, *ph1, *pffn;
    cudaGetSymbolAddress((void**)&pq,    g_q);
    cudaGetSymbolAddress((void**)&pk,    g_k);
    cudaGetSymbolAddress((void**)&pv,    g_v);
    cudaGetSymbolAddress((void**)&pattn, g_attn);
    cudaGetSymbolAddress((void**)&ph1,   g_h1);
    cudaGetSymbolAddress((void**)&pffn,  g_ffn);

    cudaFuncSetAttribute(gemm_mma<128,0>, cudaFuncAttributeMaxDynamicSharedMemorySize, SMEM_NT128);
    cudaFuncSetAttribute(gemm_mma<128,1>, cudaFuncAttributeMaxDynamicSharedMemorySize, SMEM_NT128);
    cudaFuncSetAttribute(gemm_mma<64,2>,  cudaFuncAttributeMaxDynamicSharedMemorySize, SMEM_PV);

    const float isq = 0.125f;  // 1/sqrt(64)

    // QKV projections
    gemm_mma<128,0><<<dim3(DIM/128, MTOK/128), 256, SMEM_NT128>>>(
        x, Wq, bq, nullptr, pq, DIM, DIM, DIM, DIM, isq, 0);
    gemm_mma<128,0><<<dim3(DIM/128, MTOK/128), 256, SMEM_NT128>>>(
        x, Wk, bk, nullptr, pk, DIM, DIM, DIM, DIM, 1.f, 0);
    gemm_mma<128,0><<<dim3(DIM/128, MTOK/128), 256, SMEM_NT128>>>(
        x, Wv, bv, nullptr, pv, DIM, DIM, DIM, DIM, 1.f, 0);

    // raw scores -> score region of d_out (per-head batched)
    gemm_mma<128,1><<<dim3(SEQ/128, SEQ/128, BSZ*NH), 256, SMEM_NT128>>>(
        pq, pk, nullptr, nullptr, score, DH, DIM, DIM, SEQ, 1.f, 0);
    softmax_mask_last<<<BSZ*NH*SEQ, 256>>>(score);
    // PV (NN)
    gemm_mma<64,2><<<dim3(1, SEQ/128, BSZ*NH), 256, SMEM_PV>>>(
        score, pv, nullptr, nullptr, pattn, SEQ, SEQ, DIM, DIM, 1.f, 0);

    // output projection + residual, LN1
    gemm_mma<128,0><<<dim3(DIM/128, MTOK/128), 256, SMEM_NT128>>>(
        pattn, Wf, bf, x, ph1, DIM, DIM, DIM, DIM, 1.f, 0);
    layernorm_row<<<MTOK, 256>>>(ph1, ph1, g1, be1);

    // FFN
    gemm_mma<128,0><<<dim3(FFD/128, MTOK/128), 256, SMEM_NT128>>>(
        ph1, W1, b1, nullptr, pffn, DIM, DIM, DIM, FFD, 1.f, 1);
    gemm_mma<128,0><<<dim3(DIM/128, MTOK/128), 256, SMEM_NT128>>>(
        pffn, W2, b2, ph1, pq, FFD, FFD, FFD, DIM, 1.f, 0);
    layernorm_row<<<MTOK, 256>>>(pq, out, g2, be2);
}

// round 6
// speedup vs baseline: 6.6435x; 1.0657x over previous
#include <cuda_runtime.h>
#include <cstdint>
#include <math.h>

#define BSZ 8
#define SEQ 1024
#define DIM 1024
#define NH 16
#define DH 64
#define MTOK (BSZ*SEQ)        // 8192
#define FFD  (2*DIM)          // 2048

// ---------------- scratch (device globals; no runtime allocation) ----------
__device__ float g_q[MTOK*DIM];
__device__ float g_k[MTOK*DIM];
__device__ float g_v[MTOK*DIM];
__device__ float g_attn[MTOK*DIM];
__device__ float g_h1[MTOK*DIM];
__device__ float g_ffn[MTOK*FFD];
__device__ float g_xr[MTOK*DIM];          // tf32-rounded x
__device__ float g_wr[8*1024*1024];       // rounded weights: Wq,Wk,Wv,Wf,W1,W2

// ================= helpers =================================================
__device__ __forceinline__ uint32_t smem_u32(const void* p) {
    uint32_t a;
    asm("{ .reg .u64 t; cvta.to.shared.u64 t, %1; cvt.u32.u64 %0, t; }"
        : "=r"(a) : "l"(p));
    return a;
}
__device__ __forceinline__ float cvtf(float x) {
    uint32_t u; asm("cvt.rna.tf32.f32 %0, %1;" : "=r"(u) : "f"(x));
    return __uint_as_float(u);
}
#define CP_ASYNC16(s, g) \
    asm volatile("cp.async.cg.shared.global [%0], [%1], 16;" :: "r"(s), "l"(g))
#define CP_COMMIT() asm volatile("cp.async.commit_group;")
#define CP_WAIT1()  asm volatile("cp.async.wait_group 1;")

__device__ __forceinline__ void mma_tf32(float* d, const uint32_t* a, const uint32_t* b) {
    asm volatile(
        "mma.sync.aligned.m16n8k8.row.col.f32.tf32.tf32.f32 "
        "{%0,%1,%2,%3}, {%4,%5,%6,%7}, {%8,%9}, {%0,%1,%2,%3};"
        : "+f"(d[0]), "+f"(d[1]), "+f"(d[2]), "+f"(d[3])
        : "r"(a[0]), "r"(a[1]), "r"(a[2]), "r"(a[3]), "r"(b[0]), "r"(b[1]));
}

// ================= tf32 pre-round pass =====================================
__global__ __launch_bounds__(256) void round_copy(
    const float* __restrict__ in, float* __restrict__ out, int n4)
{
    int i = blockIdx.x * blockDim.x + threadIdx.x;
    int stride = gridDim.x * blockDim.x;
    for (; i < n4; i += stride) {
        float4 v = ((const float4*)in)[i];
        v.x = cvtf(v.x); v.y = cvtf(v.y); v.z = cvtf(v.z); v.w = cvtf(v.w);
        ((float4*)out)[i] = v;
    }
}

// ================= mma.sync tf32 GEMM ======================================
// C[M,N] = (A[M,K] * B^T + bias) * scale (+res) (+relu) (+tf32-round)
// MODE 0: plain NT gemm (B is [N,K] row-major).
// MODE 1: per-head scores: A=q,B=k slices (lda=ldb=DIM), C=score+z*SEQ*SEQ.
// MODE 2: PV: A=P [M,K] (lda=SEQ), B=V [K,N] row-major (NN gemm), NT=64.
// All A/B operands must already be tf32-rounded; mainloop feeds raw bits.
template <int NT, int MODE>
__global__ __launch_bounds__(256, 2) void gemm_mma(
    const float* __restrict__ A, const float* __restrict__ B,
    const float* __restrict__ bias, const float* __restrict__ res,
    float* __restrict__ C, int K, int lda, int ldb, int ldc,
    float scale, int relu, int roundC)
{
    constexpr int ASTR = 36;
    constexpr int BSTR = (MODE == 2) ? 72 : 36;
    constexpr int AFL  = 128 * ASTR;
    constexpr int BFL  = (MODE == 2) ? 32 * BSTR : NT * BSTR;

    constexpr int WROWS = (NT == 128) ? 2 : 4;
    constexpr int WCOLS = 8 / WROWS;
    constexpr int WM = 128 / WROWS;
    constexpr int WN = NT / WCOLS;
    constexpr int MT  = WM / 16;
    constexpr int NTg = WN / 8;

    extern __shared__ char dynsmem[];
    float* const AsB = (float*)dynsmem;
    float* const BsB = AsB + 2 * AFL;

    const int tid = threadIdx.x;
    const int wid = tid >> 5, lane = tid & 31;
    const int g = lane >> 2, t = lane & 3;
    const int wm = (wid % WROWS) * WM;
    const int wn = (wid / WROWS) * WN;

    const int n0 = blockIdx.x * NT;
    const int m0 = blockIdx.y * 128;
    const float* Ap; const float* Bp; float* Cp;
    if (MODE == 0) { Ap = A; Bp = B; Cp = C; }
    else if (MODE == 1) {
        const int z = blockIdx.z, b = z >> 4, h = z & 15;
        Ap = A + (size_t)b * SEQ * DIM + h * DH;
        Bp = B + (size_t)b * SEQ * DIM + h * DH;
        Cp = C + (size_t)z * SEQ * SEQ;
    } else {
        const int z = blockIdx.z, b = z >> 4, h = z & 15;
        Ap = A + (size_t)z * SEQ * SEQ;
        Bp = B + (size_t)b * SEQ * DIM + h * DH;
        Cp = C + (size_t)b * SEQ * DIM + h * DH;
    }

    float acc[MT][NTg][4];
#pragma unroll
    for (int i = 0; i < MT; i++)
#pragma unroll
        for (int j = 0; j < NTg; j++)
#pragma unroll
            for (int q = 0; q < 4; q++) acc[i][j][q] = 0.f;

    const int Kc = K >> 5;

    auto load_slab = [&](int c, int buf) {
        const int kt = c << 5;
        float* As = AsB + buf * AFL;
        float* Bs = BsB + buf * BFL;
#pragma unroll
        for (int i = 0; i < 4; i++) {
            const int lin = i * 256 + tid;
            const int row = lin >> 3, c16 = lin & 7;
            const float* gp = Ap + (size_t)(m0 + row) * lda + kt + c16 * 4;
            CP_ASYNC16(smem_u32(As + row * ASTR + c16 * 4), gp);
        }
        if (MODE != 2) {
#pragma unroll
            for (int i = 0; i < NT / 32; i++) {
                const int lin = i * 256 + tid;
                const int row = lin >> 3, c16 = lin & 7;
                const float* gp = Bp + (size_t)(n0 + row) * ldb + kt + c16 * 4;
                CP_ASYNC16(smem_u32(Bs + row * BSTR + c16 * 4), gp);
            }
        } else {
#pragma unroll
            for (int i = 0; i < 2; i++) {
                const int lin = i * 256 + tid;
                const int krow = lin >> 4, c16 = lin & 15;
                const float* gp = Bp + (size_t)(kt + krow) * ldb + c16 * 4;
                CP_ASYNC16(smem_u32(Bs + krow * BSTR + c16 * 4), gp);
            }
        }
    };

    load_slab(0, 0);
    CP_COMMIT();

    for (int c = 0; c < Kc; c++) {
        if (c + 1 < Kc) load_slab(c + 1, (c + 1) & 1);
        CP_COMMIT();
        CP_WAIT1();
        __syncthreads();

        const float* As = AsB + (c & 1) * AFL;
        const float* Bs = BsB + (c & 1) * BFL;
#pragma unroll
        for (int ks = 0; ks < 4; ks++) {
            const int kk = ks * 8;
            uint32_t af[MT][4];
#pragma unroll
            for (int mt = 0; mt < MT; mt++) {
                const float* ar = As + (wm + mt * 16 + g) * ASTR + kk + t;
                af[mt][0] = __float_as_uint(ar[0]);
                af[mt][1] = __float_as_uint(ar[8 * ASTR]);
                af[mt][2] = __float_as_uint(ar[4]);
                af[mt][3] = __float_as_uint(ar[8 * ASTR + 4]);
            }
            uint32_t bf[NTg][2];
#pragma unroll
            for (int nt = 0; nt < NTg; nt++) {
                if (MODE != 2) {
                    const float* br = Bs + (wn + nt * 8 + g) * BSTR + kk + t;
                    bf[nt][0] = __float_as_uint(br[0]);
                    bf[nt][1] = __float_as_uint(br[4]);
                } else {
                    const float* br = Bs + (kk + t) * BSTR + wn + nt * 8 + g;
                    bf[nt][0] = __float_as_uint(br[0]);
                    bf[nt][1] = __float_as_uint(br[4 * BSTR]);
                }
            }
#pragma unroll
            for (int mt = 0; mt < MT; mt++)
#pragma unroll
                for (int nt = 0; nt < NTg; nt++)
                    mma_tf32(acc[mt][nt], af[mt], bf[nt]);
        }
        __syncthreads();
    }

    // ---- epilogue ----
#pragma unroll
    for (int mt = 0; mt < MT; mt++) {
        const int row = m0 + wm + mt * 16 + g;
#pragma unroll
        for (int nt = 0; nt < NTg; nt++) {
            const int col = n0 + wn + nt * 8 + 2 * t;
            float o0 = acc[mt][nt][0], o1 = acc[mt][nt][1];
            float o2 = acc[mt][nt][2], o3 = acc[mt][nt][3];
            if (bias) {
                const float b0 = bias[col], b1 = bias[col + 1];
                o0 += b0; o1 += b1; o2 += b0; o3 += b1;
            }
            if (scale != 1.f) { o0 *= scale; o1 *= scale; o2 *= scale; o3 *= scale; }
            if (res) {
                float2 r0 = *(const float2*)&res[(size_t)row * ldc + col];
                float2 r1 = *(const float2*)&res[(size_t)(row + 8) * ldc + col];
                o0 += r0.x; o1 += r0.y; o2 += r1.x; o3 += r1.y;
            }
            if (relu) {
                o0 = fmaxf(o0, 0.f); o1 = fmaxf(o1, 0.f);
                o2 = fmaxf(o2, 0.f); o3 = fmaxf(o3, 0.f);
            }
            if (roundC) {
                o0 = cvtf(o0); o1 = cvtf(o1); o2 = cvtf(o2); o3 = cvtf(o3);
            }
            *(float2*)&Cp[(size_t)row * ldc + col]       = make_float2(o0, o1);
            *(float2*)&Cp[(size_t)(row + 8) * ldc + col] = make_float2(o2, o3);
        }
    }
}

// ================= softmax (row, last col masked, tf32-rounded out) ========
__global__ __launch_bounds__(256) void softmax_mask_last(float* __restrict__ s)
{
    __shared__ float sm[8];
    const size_t base = (size_t)blockIdx.x * SEQ;
    const int tid = threadIdx.x;
    const int lane = tid & 31, wid = tid >> 5;

    float4 v = *(const float4*)&s[base + tid*4];
    const bool haslast = (tid == 255);
    if (haslast) v.w = -INFINITY;

    float m = fmaxf(fmaxf(v.x, v.y), fmaxf(v.z, v.w));
#pragma unroll
    for (int o = 16; o; o >>= 1) m = fmaxf(m, __shfl_xor_sync(0xffffffffu, m, o));
    if (lane == 0) sm[wid] = m;
    __syncthreads();
    if (tid == 0) {
        float tt = sm[0];
#pragma unroll
        for (int i = 1; i < 8; i++) tt = fmaxf(tt, sm[i]);
        sm[0] = tt;
    }
    __syncthreads();
    const float mall = sm[0];
    __syncthreads();

    float e0 = __expf(v.x - mall);
    float e1 = __expf(v.y - mall);
    float e2 = __expf(v.z - mall);
    float e3 = haslast ? 0.f : __expf(v.w - mall);
    float ssum = e0 + e1 + e2 + e3;
#pragma unroll
    for (int o = 16; o; o >>= 1) ssum += __shfl_xor_sync(0xffffffffu, ssum, o);
    if (lane == 0) sm[wid] = ssum;
    __syncthreads();
    if (tid == 0) {
        float tt = 0.f;
#pragma unroll
        for (int i = 0; i < 8; i++) tt += sm[i];
        sm[0] = tt;
    }
    __syncthreads();
    const float inv = 1.f / sm[0];
    *(float4*)&s[base + tid*4] =
        make_float4(cvtf(e0*inv), cvtf(e1*inv), cvtf(e2*inv), cvtf(e3*inv));
}

// ================= layernorm ==============================================
__global__ __launch_bounds__(256) void layernorm_row(
    const float* __restrict__ in, float* __restrict__ out,
    const float* __restrict__ g, const float* __restrict__ be, int roundC)
{
    __shared__ float sm[8], sq[8];
    const size_t base = (size_t)blockIdx.x * DIM;
    const int tid = threadIdx.x;
    const int lane = tid & 31, wid = tid >> 5;

    float4 v = *(const float4*)&in[base + tid*4];
    float s  = v.x + v.y + v.z + v.w;
    float s2 = v.x*v.x + v.y*v.y + v.z*v.z + v.w*v.w;
#pragma unroll
    for (int o = 16; o; o >>= 1) {
        s  += __shfl_xor_sync(0xffffffffu, s,  o);
        s2 += __shfl_xor_sync(0xffffffffu, s2, o);
    }
    if (lane == 0) { sm[wid] = s; sq[wid] = s2; }
    __syncthreads();
    if (tid == 0) {
        float tt = 0.f, t2 = 0.f;
#pragma unroll
        for (int i = 0; i < 8; i++) { tt += sm[i]; t2 += sq[i]; }
        sm[0] = tt; sq[0] = t2;
    }
    __syncthreads();
    const float mean = sm[0] * (1.f / DIM);
    const float var  = sq[0] * (1.f / DIM) - mean * mean;
    const float r = rsqrtf(var + 1e-5f);

    float4 gg = *(const float4*)&g[tid*4];
    float4 bb = *(const float4*)&be[tid*4];
    float4 o4;
    o4.x = (v.x - mean) * r * gg.x + bb.x;
    o4.y = (v.y - mean) * r * gg.y + bb.y;
    o4.z = (v.z - mean) * r * gg.z + bb.z;
    o4.w = (v.w - mean) * r * gg.w + bb.w;
    if (roundC) {
        o4.x = cvtf(o4.x); o4.y = cvtf(o4.y);
        o4.z = cvtf(o4.z); o4.w = cvtf(o4.w);
    }
    *(float4*)&out[base + tid*4] = o4;
}

// ================= launcher ================================================
static const int SMEM_NT128 = 2 * (128*36 + 128*36) * 4;     // 73728
static const int SMEM_PV    = (2 * 128*36 + 2 * 32*72) * 4;  // 55296

extern "C" void kernel_launch(void* const* d_in, const int* in_sizes, int n_in,
                              void* d_out, int out_size)
{
    const float* x  = (const float*)d_in[0];
    const float* Wq = (const float*)d_in[1];
    const float* bq = (const float*)d_in[2];
    const float* Wk = (const float*)d_in[3];
    const float* bk = (const float*)d_in[4];
    const float* Wv = (const float*)d_in[5];
    const float* bv = (const float*)d_in[6];
    const float* Wf = (const float*)d_in[7];
    const float* bf = (const float*)d_in[8];
    const float* W1 = (const float*)d_in[9];
    const float* b1 = (const float*)d_in[10];
    const float* W2 = (const float*)d_in[11];
    const float* b2 = (const float*)d_in[12];
    const float* g1 = (const float*)d_in[13];
    const float* be1= (const float*)d_in[14];
    const float* g2 = (const float*)d_in[15];
    const float* be2= (const float*)d_in[16];

    float* out   = (float*)d_out;
    float* score = out + (size_t)MTOK * DIM;

    float *pq, *pk, *pv, *pattn, *ph1, *pffn, *pxr, *pwr;
    cudaGetSymbolAddress((void**)&pq,    g_q);
    cudaGetSymbolAddress((void**)&pk,    g_k);
    cudaGetSymbolAddress((void**)&pv,    g_v);
    cudaGetSymbolAddress((void**)&pattn, g_attn);
    cudaGetSymbolAddress((void**)&ph1,   g_h1);
    cudaGetSymbolAddress((void**)&pffn,  g_ffn);
    cudaGetSymbolAddress((void**)&pxr,   g_xr);
    cudaGetSymbolAddress((void**)&pwr,   g_wr);

    float* rWq = pwr;
    float* rWk = pwr + 1*1024*1024;
    float* rWv = pwr + 2*1024*1024;
    float* rWf = pwr + 3*1024*1024;
    float* rW1 = pwr + 4*1024*1024;
    float* rW2 = pwr + 6*1024*1024;

    cudaFuncSetAttribute(gemm_mma<128,0>, cudaFuncAttributeMaxDynamicSharedMemorySize, SMEM_NT128);
    cudaFuncSetAttribute(gemm_mma<128,1>, cudaFuncAttributeMaxDynamicSharedMemorySize, SMEM_NT128);
    cudaFuncSetAttribute(gemm_mma<64,2>,  cudaFuncAttributeMaxDynamicSharedMemorySize, SMEM_PV);

    const float isq = 0.125f;  // 1/sqrt(64)

    // ---- pre-round GEMM operands to tf32 ----
    round_copy<<<2048, 256>>>(x,  pxr, MTOK*DIM/4);
    round_copy<<<1024, 256>>>(Wq, rWq, DIM*DIM/4);
    round_copy<<<1024, 256>>>(Wk, rWk, DIM*DIM/4);
    round_copy<<<1024, 256>>>(Wv, rWv, DIM*DIM/4);
    round_copy<<<1024, 256>>>(Wf, rWf, DIM*DIM/4);
    round_copy<<<2048, 256>>>(W1, rW1, FFD*DIM/4);
    round_copy<<<2048, 256>>>(W2, rW2, FFD*DIM/4);

    // QKV projections (outputs rounded: feed attention GEMMs)
    gemm_mma<128,0><<<dim3(DIM/128, MTOK/128), 256, SMEM_NT128>>>(
        pxr, rWq, bq, nullptr, pq, DIM, DIM, DIM, DIM, isq, 0, 1);
    gemm_mma<128,0><<<dim3(DIM/128, MTOK/128), 256, SMEM_NT128>>>(
        pxr, rWk, bk, nullptr, pk, DIM, DIM, DIM, DIM, 1.f, 0, 1);
    gemm_mma<128,0><<<dim3(DIM/128, MTOK/128), 256, SMEM_NT128>>>(
        pxr, rWv, bv, nullptr, pv, DIM, DIM, DIM, DIM, 1.f, 0, 1);

    // raw scores -> score region of d_out (per-head batched)
    gemm_mma<128,1><<<dim3(SEQ/128, SEQ/128, BSZ*NH), 256, SMEM_NT128>>>(
        pq, pk, nullptr, nullptr, score, DH, DIM, DIM, SEQ, 1.f, 0, 0);
    softmax_mask_last<<<BSZ*NH*SEQ, 256>>>(score);
    // PV (NN); attn rounded (feeds Wf GEMM)
    gemm_mma<64,2><<<dim3(1, SEQ/128, BSZ*NH), 256, SMEM_PV>>>(
        score, pv, nullptr, nullptr, pattn, SEQ, SEQ, DIM, DIM, 1.f, 0, 1);

    // output projection + residual (exact x), LN1 (rounded: feeds W1)
    gemm_mma<128,0><<<dim3(DIM/128, MTOK/128), 256, SMEM_NT128>>>(
        pattn, rWf, bf, x, ph1, DIM, DIM, DIM, DIM, 1.f, 0, 0);
    layernorm_row<<<MTOK, 256>>>(ph1, ph1, g1, be1, 1);

    // FFN: W1 out rounded (feeds W2); W2 out exact
    gemm_mma<128,0><<<dim3(FFD/128, MTOK/128), 256, SMEM_NT128>>>(
        ph1, rW1, b1, nullptr, pffn, DIM, DIM, DIM, FFD, 1.f, 1, 1);
    gemm_mma<128,0><<<dim3(DIM/128, MTOK/128), 256, SMEM_NT128>>>(
        pffn, rW2, b2, ph1, pq, FFD, FFD, FFD, DIM, 1.f, 0, 0);
    layernorm_row<<<MTOK, 256>>>(pq, out, g2, be2, 0);
}